// round 3
// baseline (speedup 1.0000x reference)
#include <cuda_runtime.h>
#include <cuda_bf16.h>

// Problem constants
#define NN   1024
#define II   64
#define OO   64
#define RTAIL 960          // N - I
#define TAILK 896          // rows 128..1023
#define NWARM 25
#define NB   120           // persistent blocks (<= 148 SMs, all co-resident)
#define BROWS 16384

// ---------------- device scratch (static: no allocations allowed) -------------
__device__ float d_W64[64 * 1024];      // (delta/N) * sig_diff[k<64][64+j], padded j<1024
__device__ float d_C[1024];             // per-column constant, padded zeros
__device__ float d_u[2][RTAIL];         // unnormalized warmup state ping-pong
__device__ float d_sp[NWARM + 1][NB];   // per-block partial sums of u (deterministic s)
__device__ unsigned g_barcnt = 0;
__device__ unsigned g_bargen = 0;

// ---------------- helpers ----------------------------------------------------
static __device__ __forceinline__ float sigd(float idv, float e, float iv, float b) {
    return expf(-b * fabsf(e - idv)) - expf(-b * fabsf(iv - idv));
}

static __device__ __forceinline__ void grid_barrier(int nb) {
    __threadfence();
    __syncthreads();
    if (threadIdx.x == 0) {
        unsigned gen = *(volatile unsigned*)&g_bargen;
        unsigned arrived = atomicAdd(&g_barcnt, 1u);
        if (arrived == (unsigned)(nb - 1)) {
            g_barcnt = 0;
            __threadfence();
            atomicAdd(&g_bargen, 1u);
        } else {
            while (*(volatile unsigned*)&g_bargen == gen) { __nanosleep(40); }
            __threadfence();
        }
    }
    __syncthreads();
}

static __device__ __forceinline__ unsigned long long splat2(float x) {
    unsigned long long d;
    asm("mov.b64 %0, {%1, %1};" : "=l"(d) : "f"(x));
    return d;
}
static __device__ __forceinline__ unsigned long long ffma2(unsigned long long a,
                                                           unsigned long long b,
                                                           unsigned long long c) {
    unsigned long long d;
    asm("fma.rn.f32x2 %0, %1, %2, %3;" : "=l"(d) : "l"(a), "l"(b), "l"(c));
    return d;
}
static __device__ __forceinline__ void unpack2(unsigned long long v, float& lo, float& hi) {
    asm("mov.b64 {%0, %1}, %2;" : "=f"(lo), "=f"(hi) : "l"(v));
}

// ---------------- kernel 1: sig_diff slices + 25 warmup steps + C ------------
__global__ void __launch_bounds__(256)
warm_kernel(const float* __restrict__ ids, const float* __restrict__ enh,
            const float* __restrict__ inh, const float* __restrict__ beta,
            const float* __restrict__ delta) {
    __shared__ float w_s[8 * TAILK];   // this block's 8 columns, rows 128..1023
    __shared__ float u_s[RTAIL];
    __shared__ float h_s[8];
    __shared__ float sp_s[8];

    const float b  = beta[0];
    const float dn = delta[0] * (1.0f / (float)NN);
    const int tid  = threadIdx.x;
    const int bid  = blockIdx.x;
    const int warp = tid >> 5;
    const int lane = tid & 31;
    const int j0   = bid * 8;          // tail-column base for this block

    // --- phase 0a: W64 (pre-scaled by delta/N, padded cols 960..1023 = 0) ----
    for (int idx = bid * 256 + tid; idx < 64 * 1024; idx += NB * 256) {
        int k = idx >> 10, j = idx & 1023;
        float v = 0.f;
        if (j < RTAIL) v = dn * sigd(ids[II + j], enh[k], inh[k], b);
        d_W64[idx] = v;
    }
    // --- phase 0b: block-local tail columns of sig_diff (rows 128..1023) ----
    for (int idx = tid; idx < 8 * TAILK; idx += 256) {
        int c = idx / TAILK, i = idx - c * TAILK;
        int k = 128 + i;
        w_s[idx] = sigd(ids[II + j0 + c], enh[k], inh[k], b);
    }
    // --- phase 0c: constant head term h_j = (1/N) * sum_{k<64} W[k, col] ----
    {
        float idv = ids[II + j0 + warp];
        float hv = 0.f;
        for (int k = lane; k < 64; k += 32) hv += sigd(idv, enh[k], inh[k], b);
        #pragma unroll
        for (int o = 16; o; o >>= 1) hv += __shfl_down_sync(0xffffffffu, hv, o);
        if (lane == 0) h_s[warp] = hv * (1.0f / (float)NN);
    }
    // --- phase 0d: init state ------------------------------------------------
    {
        int g = bid * 256 + tid;
        if (g < RTAIL) d_u[0][g] = 1.0f / (float)NN;
        if (tid == 0) d_sp[0][bid] = (bid == 0) ? 1.0f : 0.0f;
        if (bid == 0 && tid < 64) d_C[RTAIL + tid] = 0.f;
    }
    grid_barrier(NB);

    int cur = 0;
    for (int it = 0; it < NWARM; ++it) {
        // deterministic s = sum of per-block partials
        float sv = 0.f;
        for (int i = lane; i < NB; i += 32) sv += d_sp[it][i];
        #pragma unroll
        for (int o = 16; o; o >>= 1) sv += __shfl_down_sync(0xffffffffu, sv, o);
        sv = __shfl_sync(0xffffffffu, sv, 0);
        float inv = (sv > 0.f) ? 1.0f / sv : 1.0f;

        for (int i = tid; i < RTAIL; i += 256) u_s[i] = d_u[cur][i];
        __syncthreads();

        // one warp per column: tail dot over rows 128..1023
        float dot = 0.f;
        for (int i = lane; i < TAILK; i += 32) dot += u_s[64 + i] * w_s[warp * TAILK + i];
        #pragma unroll
        for (int o = 16; o; o >>= 1) dot += __shfl_down_sync(0xffffffffu, dot, o);
        if (lane == 0) {
            int j = j0 + warp;
            float cT = u_s[j] * inv;
            float nv = fmaxf(cT + dn * (h_s[warp] + dot * inv), 0.f);
            d_u[cur ^ 1][j] = nv;
            sp_s[warp] = nv;
        }
        __syncthreads();
        if (tid == 0) {
            float bs = 0.f;
            #pragma unroll
            for (int c = 0; c < 8; ++c) bs += sp_s[c];
            d_sp[it + 1][bid] = bs;
        }
        cur ^= 1;
        grid_barrier(NB);
    }

    // --- final: C_j = conc_j + (delta/N) * tail_dot(conc) --------------------
    {
        float sv = 0.f;
        for (int i = lane; i < NB; i += 32) sv += d_sp[NWARM][i];
        #pragma unroll
        for (int o = 16; o; o >>= 1) sv += __shfl_down_sync(0xffffffffu, sv, o);
        sv = __shfl_sync(0xffffffffu, sv, 0);
        float inv = (sv > 0.f) ? 1.0f / sv : 1.0f;

        for (int i = tid; i < RTAIL; i += 256) u_s[i] = d_u[cur][i];
        __syncthreads();

        float dot = 0.f;
        for (int i = lane; i < TAILK; i += 32) dot += u_s[64 + i] * w_s[warp * TAILK + i];
        #pragma unroll
        for (int o = 16; o; o >>= 1) dot += __shfl_down_sync(0xffffffffu, dot, o);
        if (lane == 0) {
            int j = j0 + warp;
            d_C[j] = u_s[j] * inv + dn * dot * inv;
        }
    }
}

// ---------------- kernel 2: B x 64 x 960 GEMM + relu/sum/normalize -----------
// TM=128 rows per block, 8 column chunks of 128 (cols padded to 1024),
// 16x16 threads, 8x8 micro-tile, packed f32x2 FMAs.
#define TM 128
#define NCH 128
#define AS_STRIDE 132
#define SMEM_GEMM ((64*132 + 64*132 + 128*64 + 128*17 + 128) * 4)

__global__ void __launch_bounds__(256)
gemm_kernel(const float* __restrict__ inp, float* __restrict__ out) {
    extern __shared__ float sm[];
    float* As    = sm;                        // [64][132]  A^T: As[k][row]
    float* Ws    = As + 64 * AS_STRIDE;       // [64][132]  chunk of W64
    float* out_s = Ws + 64 * AS_STRIDE;       // [128][64]  relu'd cols 0..63
    float* ssum  = out_s + 128 * 64;          // [128][17]
    float* sinv  = ssum + 128 * 17;           // [128]

    const int tid = threadIdx.x;
    const int tx = tid & 15, ty = tid >> 4;
    const int b0 = blockIdx.x * TM;

    // load A tile (transpose into As[k][row])
    for (int idx = tid; idx < TM * 64; idx += 256) {
        int row = idx >> 6, k = idx & 63;
        As[k * AS_STRIDE + row] = inp[(b0 + row) * 64 + k];
    }
    float s_part[8];
    #pragma unroll
    for (int r = 0; r < 8; ++r) s_part[r] = 0.f;
    __syncthreads();

    for (int ch = 0; ch < 8; ++ch) {
        int cbase = ch * NCH;
        for (int idx = tid; idx < 64 * NCH; idx += 256) {
            int k = idx >> 7, j = idx & 127;
            Ws[k * AS_STRIDE + j] = d_W64[k * 1024 + cbase + j];
        }
        __syncthreads();

        unsigned long long acc[8][4];
        #pragma unroll
        for (int r = 0; r < 8; ++r)
            #pragma unroll
            for (int c = 0; c < 4; ++c) acc[r][c] = 0ull;

        #pragma unroll 4
        for (int k = 0; k < 64; ++k) {
            float4 a0 = *(const float4*)&As[k * AS_STRIDE + ty * 8];
            float4 a1 = *(const float4*)&As[k * AS_STRIDE + ty * 8 + 4];
            ulonglong2 w01 = *(const ulonglong2*)&Ws[k * AS_STRIDE + tx * 8];
            ulonglong2 w23 = *(const ulonglong2*)&Ws[k * AS_STRIDE + tx * 8 + 4];
            unsigned long long sp[8];
            sp[0] = splat2(a0.x); sp[1] = splat2(a0.y);
            sp[2] = splat2(a0.z); sp[3] = splat2(a0.w);
            sp[4] = splat2(a1.x); sp[5] = splat2(a1.y);
            sp[6] = splat2(a1.z); sp[7] = splat2(a1.w);
            #pragma unroll
            for (int r = 0; r < 8; ++r) {
                acc[r][0] = ffma2(sp[r], w01.x, acc[r][0]);
                acc[r][1] = ffma2(sp[r], w01.y, acc[r][1]);
                acc[r][2] = ffma2(sp[r], w23.x, acc[r][2]);
                acc[r][3] = ffma2(sp[r], w23.y, acc[r][3]);
            }
        }

        // epilogue: v = relu(C + acc), accumulate row sums, save cols < 64
        float cv[8];
        #pragma unroll
        for (int cc = 0; cc < 8; ++cc) cv[cc] = d_C[cbase + tx * 8 + cc];
        const bool store0 = (ch == 0) && (tx < 8);
        #pragma unroll
        for (int r = 0; r < 8; ++r) {
            int row = ty * 8 + r;
            #pragma unroll
            for (int cp = 0; cp < 4; ++cp) {
                float lo, hi;
                unpack2(acc[r][cp], lo, hi);
                float v0 = fmaxf(cv[cp * 2] + lo, 0.f);
                float v1 = fmaxf(cv[cp * 2 + 1] + hi, 0.f);
                s_part[r] += v0 + v1;
                if (store0) {
                    out_s[row * 64 + tx * 8 + cp * 2]     = v0;
                    out_s[row * 64 + tx * 8 + cp * 2 + 1] = v1;
                }
            }
        }
        __syncthreads();
    }

    #pragma unroll
    for (int r = 0; r < 8; ++r) ssum[(ty * 8 + r) * 17 + tx] = s_part[r];
    __syncthreads();
    if (tid < TM) {
        float s = 0.f;
        #pragma unroll
        for (int x = 0; x < 16; ++x) s += ssum[tid * 17 + x];
        sinv[tid] = (s > 0.f) ? 1.0f / s : 1.0f;
    }
    __syncthreads();
    for (int idx = tid; idx < TM * 64; idx += 256) {
        int row = idx >> 6, col = idx & 63;
        out[(b0 + row) * 64 + col] = out_s[row * 64 + col] * sinv[row];
    }
}

// ---------------- launch ------------------------------------------------------
extern "C" void kernel_launch(void* const* d_in, const int* in_sizes, int n_in,
                              void* d_out, int out_size) {
    const float* inputs = (const float*)d_in[0];
    const float* ids    = (const float*)d_in[1];
    const float* enh    = (const float*)d_in[2];
    const float* inh    = (const float*)d_in[3];
    const float* beta   = (const float*)d_in[4];
    const float* delta  = (const float*)d_in[5];

    cudaFuncSetAttribute(gemm_kernel, cudaFuncAttributeMaxDynamicSharedMemorySize,
                         SMEM_GEMM);

    warm_kernel<<<NB, 256>>>(ids, enh, inh, beta, delta);
    gemm_kernel<<<BROWS / TM, 256, SMEM_GEMM>>>(inputs, (float*)d_out);
}

// round 4
// speedup vs baseline: 1.2848x; 1.2848x over previous
#include <cuda_runtime.h>
#include <cuda_bf16.h>

// Problem constants
#define NN    1024
#define II    64
#define OO    64
#define RTAIL 960          // N - I
#define TAILK 896          // rows 128..1023
#define NWARM 25
#define NB    60           // persistent warm blocks (all co-resident)
#define COLSB 16           // tail columns per warm block (2 per warp)
#define BROWS 16384

// ---------------- device scratch (static: no allocations allowed) -------------
__device__ float d_W64[64 * 1024];       // (delta/N)*sig_diff[k<64][64+j], pad j<1024
__device__ float d_C[1024];              // per-column constant, padded zeros
__device__ float d_u[2][RTAIL];          // unnormalized warmup state ping-pong
__device__ float d_rowpart[8 * BROWS];   // per-chunk row-sum partials
__device__ unsigned g_barcnt = 0;
__device__ unsigned g_bargen = 0;

// ---------------- helpers ----------------------------------------------------
static __device__ __forceinline__ float sigd(float idv, float e, float iv, float b) {
    return expf(-b * fabsf(e - idv)) - expf(-b * fabsf(iv - idv));
}

static __device__ __forceinline__ void grid_barrier(int nb) {
    __threadfence();
    __syncthreads();
    if (threadIdx.x == 0) {
        unsigned gen = *(volatile unsigned*)&g_bargen;
        unsigned arrived = atomicAdd(&g_barcnt, 1u);
        if (arrived == (unsigned)(nb - 1)) {
            g_barcnt = 0;
            __threadfence();
            atomicAdd(&g_bargen, 1u);
        } else {
            while (*(volatile unsigned*)&g_bargen == gen) { }
            __threadfence();
        }
    }
    __syncthreads();
}

static __device__ __forceinline__ unsigned long long splat2(float x) {
    unsigned long long d;
    asm("mov.b64 %0, {%1, %1};" : "=l"(d) : "f"(x));
    return d;
}
static __device__ __forceinline__ unsigned long long ffma2(unsigned long long a,
                                                           unsigned long long b,
                                                           unsigned long long c) {
    unsigned long long d;
    asm("fma.rn.f32x2 %0, %1, %2, %3;" : "=l"(d) : "l"(a), "l"(b), "l"(c));
    return d;
}
static __device__ __forceinline__ void unpack2(unsigned long long v, float& lo, float& hi) {
    asm("mov.b64 {%0, %1}, %2;" : "=f"(lo), "=f"(hi) : "l"(v));
}

// ---------------- kernel 1: sig_diff slices + 25 warmup steps + C ------------
// dynamic smem: w_s[COLSB*896] | u_s[960] | h_s[16] | red[8]
#define WARM_SMEM ((COLSB * TAILK + RTAIL + COLSB + 8) * 4)

__global__ void __launch_bounds__(256)
warm_kernel(const float* __restrict__ ids, const float* __restrict__ enh,
            const float* __restrict__ inh, const float* __restrict__ beta,
            const float* __restrict__ delta) {
    extern __shared__ float sm[];
    float* w_s = sm;                       // [COLSB][896]
    float* u_s = w_s + COLSB * TAILK;      // [960]
    float* h_s = u_s + RTAIL;              // [16]
    float* red = h_s + COLSB;              // [8]

    const float b  = beta[0];
    const float dn = delta[0] * (1.0f / (float)NN);
    const int tid  = threadIdx.x;
    const int bid  = blockIdx.x;
    const int warp = tid >> 5;
    const int lane = tid & 31;
    const int j0   = bid * COLSB;          // tail-column base

    // --- phase 0a: W64 (pre-scaled, padded cols 960..1023 = 0) ---------------
    for (int idx = bid * 256 + tid; idx < 64 * 1024; idx += NB * 256) {
        int k = idx >> 10, j = idx & 1023;
        float v = 0.f;
        if (j < RTAIL) v = dn * sigd(ids[II + j], enh[k], inh[k], b);
        d_W64[idx] = v;
    }
    // --- phase 0b: block-local tail columns (rows 128..1023) -----------------
    for (int idx = tid; idx < COLSB * TAILK; idx += 256) {
        int c = idx / TAILK, i = idx - c * TAILK;
        w_s[idx] = sigd(ids[II + j0 + c], enh[128 + i], inh[128 + i], b);
    }
    // --- phase 0c: head term h_c = (1/N) * sum_{k<64} W[k,col] ---------------
    {
        // warp handles cols c0 = 2*warp, c0+1
        #pragma unroll
        for (int cc = 0; cc < 2; ++cc) {
            int c = warp * 2 + cc;
            float idv = ids[II + j0 + c];
            float hv = sigd(idv, enh[lane], inh[lane], b)
                     + sigd(idv, enh[lane + 32], inh[lane + 32], b);
            #pragma unroll
            for (int o = 16; o; o >>= 1) hv += __shfl_down_sync(0xffffffffu, hv, o);
            if (lane == 0) h_s[c] = hv * (1.0f / (float)NN);
        }
    }
    // --- phase 0d: init state ------------------------------------------------
    {
        int g = bid * 256 + tid;
        if (g < RTAIL) d_u[0][g] = 1.0f / (float)NN;
        if (bid == 0 && tid < 64) d_C[RTAIL + tid] = 0.f;
    }
    grid_barrier(NB);

    const int c0 = warp * 2, c1 = c0 + 1;
    const float* w0 = &w_s[c0 * TAILK];
    const float* w1 = &w_s[c1 * TAILK];

    int cur = 0;
    for (int it = 0; it < NWARM; ++it) {
        // load u, accumulate local partial sum for s
        float p = 0.f;
        for (int i = tid; i < RTAIL; i += 256) {
            float v = d_u[cur][i];
            u_s[i] = v;
            p += v;
        }
        #pragma unroll
        for (int o = 16; o; o >>= 1) p += __shfl_down_sync(0xffffffffu, p, o);
        if (lane == 0) red[warp] = p;
        __syncthreads();
        float s = red[0] + red[1] + red[2] + red[3]
                + red[4] + red[5] + red[6] + red[7];
        float inv = (it == 0) ? 1.0f : ((s > 0.f) ? 1.0f / s : 1.0f);

        float d0 = 0.f, d1 = 0.f;
        for (int i = lane; i < TAILK; i += 32) {
            float uv = u_s[64 + i];
            d0 = fmaf(uv, w0[i], d0);
            d1 = fmaf(uv, w1[i], d1);
        }
        #pragma unroll
        for (int o = 16; o; o >>= 1) {
            d0 += __shfl_down_sync(0xffffffffu, d0, o);
            d1 += __shfl_down_sync(0xffffffffu, d1, o);
        }
        if (lane == 0) {
            float nv0 = fmaxf(u_s[j0 + c0] * inv + dn * (h_s[c0] + d0 * inv), 0.f);
            float nv1 = fmaxf(u_s[j0 + c1] * inv + dn * (h_s[c1] + d1 * inv), 0.f);
            d_u[cur ^ 1][j0 + c0] = nv0;
            d_u[cur ^ 1][j0 + c1] = nv1;
        }
        cur ^= 1;
        grid_barrier(NB);
    }

    // --- final: C_j = c_j + (delta/N)*tail_dot(c),  c = u*inv ----------------
    {
        float p = 0.f;
        for (int i = tid; i < RTAIL; i += 256) {
            float v = d_u[cur][i];
            u_s[i] = v;
            p += v;
        }
        #pragma unroll
        for (int o = 16; o; o >>= 1) p += __shfl_down_sync(0xffffffffu, p, o);
        if (lane == 0) red[warp] = p;
        __syncthreads();
        float s = red[0] + red[1] + red[2] + red[3]
                + red[4] + red[5] + red[6] + red[7];
        float inv = (s > 0.f) ? 1.0f / s : 1.0f;

        float d0 = 0.f, d1 = 0.f;
        for (int i = lane; i < TAILK; i += 32) {
            float uv = u_s[64 + i];
            d0 = fmaf(uv, w0[i], d0);
            d1 = fmaf(uv, w1[i], d1);
        }
        #pragma unroll
        for (int o = 16; o; o >>= 1) {
            d0 += __shfl_down_sync(0xffffffffu, d0, o);
            d1 += __shfl_down_sync(0xffffffffu, d1, o);
        }
        if (lane == 0) {
            d_C[j0 + c0] = u_s[j0 + c0] * inv + dn * d0 * inv;
            d_C[j0 + c1] = u_s[j0 + c1] * inv + dn * d1 * inv;
        }
    }
}

// ---------------- kernel 2: GEMM, grid = (row tiles, 8 col chunks) -----------
// TM=128 rows/block, 128 cols/block, 16x16 threads, 8x8 micro-tile, f32x2 FMA.
// Writes unnormalized out (chunk 0) + per-chunk row-sum partials.
#define TM 128
#define AS_STRIDE 132
#define SMEM_GEMM ((64 * AS_STRIDE + 64 * AS_STRIDE) * 4)

__global__ void __launch_bounds__(256)
gemm_kernel(const float* __restrict__ inp, float* __restrict__ out) {
    extern __shared__ float sm[];
    float* As = sm;                      // [64][132]  A^T: As[k][row]
    float* Ws = As + 64 * AS_STRIDE;     // [64][132]  chunk of W64

    const int tid = threadIdx.x;
    const int tx = tid & 15, ty = tid >> 4;
    const int b0 = blockIdx.x * TM;
    const int chunk = blockIdx.y;
    const int cbase = chunk * 128;

    for (int idx = tid; idx < TM * 64; idx += 256) {
        int row = idx >> 6, k = idx & 63;
        As[k * AS_STRIDE + row] = inp[(b0 + row) * 64 + k];
    }
    for (int idx = tid; idx < 64 * 128; idx += 256) {
        int k = idx >> 7, j = idx & 127;
        Ws[k * AS_STRIDE + j] = d_W64[k * 1024 + cbase + j];
    }
    __syncthreads();

    unsigned long long acc[8][4];
    #pragma unroll
    for (int r = 0; r < 8; ++r)
        #pragma unroll
        for (int c = 0; c < 4; ++c) acc[r][c] = 0ull;

    #pragma unroll 4
    for (int k = 0; k < 64; ++k) {
        float4 a0 = *(const float4*)&As[k * AS_STRIDE + ty * 8];
        float4 a1 = *(const float4*)&As[k * AS_STRIDE + ty * 8 + 4];
        ulonglong2 w01 = *(const ulonglong2*)&Ws[k * AS_STRIDE + tx * 8];
        ulonglong2 w23 = *(const ulonglong2*)&Ws[k * AS_STRIDE + tx * 8 + 4];
        unsigned long long sp[8];
        sp[0] = splat2(a0.x); sp[1] = splat2(a0.y);
        sp[2] = splat2(a0.z); sp[3] = splat2(a0.w);
        sp[4] = splat2(a1.x); sp[5] = splat2(a1.y);
        sp[6] = splat2(a1.z); sp[7] = splat2(a1.w);
        #pragma unroll
        for (int r = 0; r < 8; ++r) {
            acc[r][0] = ffma2(sp[r], w01.x, acc[r][0]);
            acc[r][1] = ffma2(sp[r], w01.y, acc[r][1]);
            acc[r][2] = ffma2(sp[r], w23.x, acc[r][2]);
            acc[r][3] = ffma2(sp[r], w23.y, acc[r][3]);
        }
    }

    // epilogue: v = relu(C + acc); row-sum partial; chunk 0 stores unnorm out
    float cv[8];
    #pragma unroll
    for (int cc = 0; cc < 8; ++cc) cv[cc] = d_C[cbase + tx * 8 + cc];
    const bool store0 = (chunk == 0) && (tx < 8);

    float s_part[8];
    #pragma unroll
    for (int r = 0; r < 8; ++r) {
        int row = ty * 8 + r;
        float sp_r = 0.f;
        #pragma unroll
        for (int cp = 0; cp < 4; ++cp) {
            float lo, hi;
            unpack2(acc[r][cp], lo, hi);
            float v0 = fmaxf(cv[cp * 2] + lo, 0.f);
            float v1 = fmaxf(cv[cp * 2 + 1] + hi, 0.f);
            sp_r += v0 + v1;
            if (store0) {
                out[(b0 + row) * 64 + tx * 8 + cp * 2]     = v0;
                out[(b0 + row) * 64 + tx * 8 + cp * 2 + 1] = v1;
            }
        }
        s_part[r] = sp_r;
    }
    // reduce across the 16 tx lanes (threads with same ty are contiguous lanes)
    #pragma unroll
    for (int r = 0; r < 8; ++r) {
        #pragma unroll
        for (int m = 8; m; m >>= 1)
            s_part[r] += __shfl_xor_sync(0xffffffffu, s_part[r], m, 16);
    }
    if (tx == 0) {
        #pragma unroll
        for (int r = 0; r < 8; ++r)
            d_rowpart[chunk * BROWS + b0 + ty * 8 + r] = s_part[r];
    }
}

// ---------------- kernel 3: normalize rows (in-place on out) -----------------
__global__ void __launch_bounds__(256)
scale_kernel(float* __restrict__ out) {
    __shared__ float inv_s[256];
    const int tid = threadIdx.x;
    const int base = blockIdx.x * 256;

    float s = 0.f;
    #pragma unroll
    for (int c = 0; c < 8; ++c) s += d_rowpart[c * BROWS + base + tid];
    inv_s[tid] = (s > 0.f) ? 1.0f / s : 1.0f;
    __syncthreads();

    for (int idx = tid; idx < 256 * 64; idx += 256) {
        int r = idx >> 6;
        out[base * 64 + idx] *= inv_s[r];
    }
}

// ---------------- launch ------------------------------------------------------
extern "C" void kernel_launch(void* const* d_in, const int* in_sizes, int n_in,
                              void* d_out, int out_size) {
    const float* inputs = (const float*)d_in[0];
    const float* ids    = (const float*)d_in[1];
    const float* enh    = (const float*)d_in[2];
    const float* inh    = (const float*)d_in[3];
    const float* beta   = (const float*)d_in[4];
    const float* delta  = (const float*)d_in[5];

    cudaFuncSetAttribute(warm_kernel, cudaFuncAttributeMaxDynamicSharedMemorySize,
                         WARM_SMEM);
    cudaFuncSetAttribute(gemm_kernel, cudaFuncAttributeMaxDynamicSharedMemorySize,
                         SMEM_GEMM);

    warm_kernel<<<NB, 256, WARM_SMEM>>>(ids, enh, inh, beta, delta);

    dim3 grid(BROWS / TM, 8);
    gemm_kernel<<<grid, 256, SMEM_GEMM>>>(inputs, (float*)d_out);

    scale_kernel<<<BROWS / 256, 256>>>((float*)d_out);
}